// round 4
// baseline (speedup 1.0000x reference)
#include <cuda_runtime.h>
#include <cuda_bf16.h>
#include <math.h>

#define BB   64
#define TL   383
#define SL   384
#define DL   896
#define HG   400
#define HEH  256
#define TAGL 128
#define MST  20
#define MR   (BB*SL)   // 24576

// ---------------- scratch (device globals; no allocation allowed) ----------------
__device__ float g_X[(size_t)MR*DL];
__device__ float g_Mf[MR];
__device__ float g_PreF[(size_t)MR*HG];
__device__ float g_PreB[(size_t)MR*HG];
__device__ float g_GS[(size_t)MR*2*HG];
__device__ float g_H[2*2*BB*HG];          // [dir][pingpong][b*HG+j]
__device__ float g_He0[(size_t)MR*HEH];
__device__ float g_He1[(size_t)MR*HEH];
__device__ float g_Ap[MR*MST];
__device__ float g_WihfT[DL*HG];
__device__ float g_WihbT[DL*HG];
__device__ float g_Wg2eT[2*HG*HEH];
__device__ float g_WhheT[HEH*HEH];
__device__ float g_WhtT[2*HG*TAGL];
__device__ float g_WdtT[2*HG*TAGL];
__device__ float g_biasF[HG];
__device__ float g_biasB[HG];
__device__ float g_biasE[HEH];

#define CLUSTER_SYNC_() do { \
    asm volatile("barrier.cluster.arrive.aligned;" ::: "memory"); \
    asm volatile("barrier.cluster.wait.aligned;" ::: "memory"); \
} while (0)

// ---------------- small prep kernels ----------------
__global__ void k_transpose(const float* __restrict__ W, float* __restrict__ WT, int R, int C) {
    int idx = blockIdx.x * blockDim.x + threadIdx.x;
    if (idx < R * C) { int r = idx / C, c = idx % C; WT[(size_t)c * R + r] = W[idx]; }
}

__global__ void k_vecadd(const float* __restrict__ a, const float* __restrict__ b,
                         float* __restrict__ o, int n) {
    int i = blockIdx.x * blockDim.x + threadIdx.x;
    if (i < n) o[i] = a[i] + b[i];
}

__global__ void k_buildx(const float* __restrict__ inp, const float* __restrict__ tag,
                         const float* __restrict__ sent) {
    size_t idx = (size_t)blockIdx.x * blockDim.x + threadIdx.x;
    if (idx >= (size_t)MR * DL) return;
    int d = (int)(idx % DL);
    int m = (int)(idx / DL);
    int b = m / SL, s = m % SL;
    float v;
    if (s == 0) v = sent[d];
    else {
        int t = s - 1;
        v = (d < 768) ? inp[(size_t)(b * TL + t) * 768 + d]
                      : tag[(size_t)(b * TL + t) * TAGL + (d - 768)];
    }
    g_X[idx] = v;
}

__global__ void k_buildmf(const int* __restrict__ mask) {
    int idx = blockIdx.x * blockDim.x + threadIdx.x;
    if (idx >= MR) return;
    int b = idx / SL, s = idx % SL;
    g_Mf[idx] = (s == 0) ? 1.0f : (float)mask[b * TL + s - 1];
}

// ---------------- generic SGEMM: C(M,N) = A(M,K) @ Bt(K,N) + bias, opt ELU ----------------
template <int ACT>
__global__ __launch_bounds__(256) void k_sgemm(const float* __restrict__ A,
                                               const float* __restrict__ Bt,
                                               const float* __restrict__ bias,
                                               float* __restrict__ C, int N, int K) {
    __shared__ __align__(16) float As[16][132];
    __shared__ __align__(16) float Bs[16][64];
    int m0 = blockIdx.y * 128;
    int n0 = blockIdx.x * 64;
    int tid = threadIdx.x;
    int tx = tid & 15, ty = tid >> 4;
    float acc[8][4];
#pragma unroll
    for (int i = 0; i < 8; i++)
#pragma unroll
        for (int j = 0; j < 4; j++) acc[i][j] = 0.f;

    for (int k0 = 0; k0 < K; k0 += 16) {
#pragma unroll
        for (int it = 0; it < 2; it++) {
            int idx = tid + it * 256;
            int row = idx >> 2, c4 = idx & 3;
            float4 v = *(const float4*)(A + (size_t)(m0 + row) * K + k0 + c4 * 4);
            As[c4 * 4 + 0][row] = v.x;
            As[c4 * 4 + 1][row] = v.y;
            As[c4 * 4 + 2][row] = v.z;
            As[c4 * 4 + 3][row] = v.w;
        }
        {
            int kk = tid >> 4, n4 = tid & 15;
            int col = n0 + n4 * 4;
            float4 v = make_float4(0.f, 0.f, 0.f, 0.f);
            if (col + 3 < N) v = *(const float4*)(Bt + (size_t)(k0 + kk) * N + col);
            else {
                if (col     < N) v.x = Bt[(size_t)(k0 + kk) * N + col];
                if (col + 1 < N) v.y = Bt[(size_t)(k0 + kk) * N + col + 1];
                if (col + 2 < N) v.z = Bt[(size_t)(k0 + kk) * N + col + 2];
            }
            *(float4*)&Bs[kk][n4 * 4] = v;
        }
        __syncthreads();
#pragma unroll
        for (int kk = 0; kk < 16; kk++) {
            float a[8], bv[4];
            *(float4*)(a)     = *(const float4*)&As[kk][ty * 8];
            *(float4*)(a + 4) = *(const float4*)&As[kk][ty * 8 + 4];
            *(float4*)(bv)    = *(const float4*)&Bs[kk][tx * 4];
#pragma unroll
            for (int i = 0; i < 8; i++)
#pragma unroll
                for (int j = 0; j < 4; j++) acc[i][j] += a[i] * bv[j];
        }
        __syncthreads();
    }
#pragma unroll
    for (int i = 0; i < 8; i++) {
        int row = m0 + ty * 8 + i;
#pragma unroll
        for (int j = 0; j < 4; j++) {
            int col = n0 + tx * 4 + j;
            if (col < N) {
                float v = acc[i][j] + bias[col];
                if (ACT == 1) v = (v > 0.f) ? v : expm1f(v);
                C[(size_t)row * N + col] = v;
            }
        }
    }
}

// ---------------- persistent bidirectional masked RNN (cluster-synced) ----------------
// grid: 128 blocks; cluster = 8 consecutive blocks = one (dir, batch-group),
// CTAs within a cluster split the hidden dim j into 8 groups of 50.
__global__ void __cluster_dims__(8, 1, 1) __launch_bounds__(256, 1)
k_rnn(const float* __restrict__ WhhF, const float* __restrict__ WhhB) {
    int bx = blockIdx.x;
    int dir = bx >> 6;
    int bid = bx & 63;
    int bg = bid >> 3;      // batch group (8 batches)
    int jg = bid & 7;       // j group within cluster
    const float* Whh = dir ? WhhB : WhhF;
    const float* Pre = dir ? g_PreB : g_PreF;
    int jbase = jg * 50, b0 = bg * 8;
    int tid = threadIdx.x;
    int jl = tid >> 3, kp = tid & 7;
    bool jact = (jl < 25);
    int j0 = jbase + jl * 2;

    float w0[50], w1[50];
    if (jact) {
#pragma unroll
        for (int i = 0; i < 50; i++) {
            w0[i] = Whh[(size_t)j0 * HG + kp * 50 + i];
            w1[i] = Whh[(size_t)(j0 + 1) * HG + kp * 50 + i];
        }
    }
    float* Hp0 = g_H + dir * 2 * BB * HG;
    float* Hp1 = Hp0 + BB * HG;
    // zero-init this block's slice of BOTH H buffers.
    // FIX: strided loop — blockDim is 256 but the slice has 400 entries;
    // the previous `if (tid < 400)` left rows b0+5..b0+7 holding the previous
    // call's final hidden states, which poisoned every graph replay.
    for (int idx = tid; idx < 400; idx += 256) {
        int bl = idx / 50, jj = idx % 50;
        __stcg(&Hp0[(b0 + bl) * HG + jbase + jj], 0.f);
        __stcg(&Hp1[(b0 + bl) * HG + jbase + jj], 0.f);
    }
    CLUSTER_SYNC_();

    __shared__ __align__(16) float Hs[8 * HG];

    for (int tv = 0; tv < SL; tv++) {
        int t = dir ? (SL - 1 - tv) : tv;
        float* Hcur = (tv & 1) ? Hp1 : Hp0;
        float* Hnxt = (tv & 1) ? Hp0 : Hp1;
        // stage H tile (rows b0..b0+7, all 400 j) to shared; L2-coherent reads
        for (int idx = tid; idx < 8 * HG; idx += 256)
            Hs[idx] = __ldcg(&Hcur[(b0 + (idx / HG)) * HG + (idx % HG)]);
        __syncthreads();

        float s0v[8], s1v[8];
        if (jact) {
#pragma unroll
            for (int bl = 0; bl < 8; bl++) {
                const float2* hv = (const float2*)(Hs + bl * HG + kp * 50);
                float a0 = 0.f, a1 = 0.f, c0 = 0.f, c1 = 0.f;
#pragma unroll
                for (int i = 0; i < 25; i++) {
                    float2 h = hv[i];
                    a0 += w0[2 * i] * h.x;  c0 += w0[2 * i + 1] * h.y;
                    a1 += w1[2 * i] * h.x;  c1 += w1[2 * i + 1] * h.y;
                }
                s0v[bl] = a0 + c0;
                s1v[bl] = a1 + c1;
            }
        } else {
#pragma unroll
            for (int bl = 0; bl < 8; bl++) { s0v[bl] = 0.f; s1v[bl] = 0.f; }
        }
#pragma unroll
        for (int bl = 0; bl < 8; bl++) {
            float s0 = s0v[bl], s1 = s1v[bl];
            s0 += __shfl_xor_sync(0xffffffffu, s0, 1);
            s0 += __shfl_xor_sync(0xffffffffu, s0, 2);
            s0 += __shfl_xor_sync(0xffffffffu, s0, 4);
            s1 += __shfl_xor_sync(0xffffffffu, s1, 1);
            s1 += __shfl_xor_sync(0xffffffffu, s1, 2);
            s1 += __shfl_xor_sync(0xffffffffu, s1, 4);
            if (jact && kp == 0) {
                int b = b0 + bl;
                int mrow = b * SL + t;
                float mt = g_Mf[mrow];
                float om = 1.f - mt;
                size_t pbase = (size_t)mrow * HG;
                float h00 = Hs[bl * HG + j0];
                float h01 = Hs[bl * HG + j0 + 1];
                float hn0 = tanhf(Pre[pbase + j0] + s0);
                float hn1 = tanhf(Pre[pbase + j0 + 1] + s1);
                float u0 = mt * hn0 + om * h00;
                float u1 = mt * hn1 + om * h01;
                __stcg(&Hnxt[b * HG + j0], u0);
                __stcg(&Hnxt[b * HG + j0 + 1], u1);
                size_t gbase = (size_t)mrow * (2 * HG) + dir * HG;
                g_GS[gbase + j0] = u0 * mt;
                g_GS[gbase + j0 + 1] = u1 * mt;
            }
        }
        CLUSTER_SYNC_();   // HW release/acquire: publishes Hnxt to cluster peers
    }
}

// ---------------- estep: hn = tanh(He@Whh_e^T + be + xe*wie); logit fused ----------------
__global__ __launch_bounds__(256) void k_estep(const float* __restrict__ Hin,
                                               float* __restrict__ Hout,
                                               const float* __restrict__ wie,
                                               const float* __restrict__ wcls,
                                               const float* __restrict__ bcls,
                                               const float* __restrict__ bos, int step) {
    __shared__ __align__(16) float As[16][68];
    __shared__ __align__(16) float Bs[16][256];
    int m0 = blockIdx.x * 64;
    int tid = threadIdx.x;
    int tx = tid & 31, ty = tid >> 5;
    float acc[8][8];
#pragma unroll
    for (int i = 0; i < 8; i++)
#pragma unroll
        for (int j = 0; j < 8; j++) acc[i][j] = 0.f;

    for (int k0 = 0; k0 < HEH; k0 += 16) {
        {
            int row = tid >> 2, c4 = tid & 3;
            float4 v = *(const float4*)(Hin + (size_t)(m0 + row) * HEH + k0 + c4 * 4);
            As[c4 * 4 + 0][row] = v.x;
            As[c4 * 4 + 1][row] = v.y;
            As[c4 * 4 + 2][row] = v.z;
            As[c4 * 4 + 3][row] = v.w;
        }
#pragma unroll
        for (int it = 0; it < 4; it++) {
            int idx = tid + it * 256;
            int kk = idx >> 6, n4 = idx & 63;
            *(float4*)&Bs[kk][n4 * 4] =
                *(const float4*)(g_WhheT + (size_t)(k0 + kk) * HEH + n4 * 4);
        }
        __syncthreads();
#pragma unroll
        for (int kk = 0; kk < 16; kk++) {
            float a[8], bv[8];
            *(float4*)(a)      = *(const float4*)&As[kk][ty * 8];
            *(float4*)(a + 4)  = *(const float4*)&As[kk][ty * 8 + 4];
            *(float4*)(bv)     = *(const float4*)&Bs[kk][tx * 8];
            *(float4*)(bv + 4) = *(const float4*)&Bs[kk][tx * 8 + 4];
#pragma unroll
            for (int i = 0; i < 8; i++)
#pragma unroll
                for (int j = 0; j < 8; j++) acc[i][j] += a[i] * bv[j];
        }
        __syncthreads();
    }
    float bcl = bcls[0];
#pragma unroll
    for (int i = 0; i < 8; i++) {
        int row = m0 + ty * 8 + i;
        float xe = (step == 0) ? bos[0] : g_Ap[row * MST + step - 1];
        float part = 0.f;
        float hn[8];
#pragma unroll
        for (int j = 0; j < 8; j++) {
            int col = tx * 8 + j;
            float v = tanhf(acc[i][j] + g_biasE[col] + xe * wie[col]);
            hn[j] = v;
            part += v * wcls[col];
        }
        float4 p0 = make_float4(hn[0], hn[1], hn[2], hn[3]);
        float4 p1 = make_float4(hn[4], hn[5], hn[6], hn[7]);
        *(float4*)(Hout + (size_t)row * HEH + tx * 8)     = p0;
        *(float4*)(Hout + (size_t)row * HEH + tx * 8 + 4) = p1;
#pragma unroll
        for (int off = 16; off > 0; off >>= 1)
            part += __shfl_xor_sync(0xffffffffu, part, off);
        if (tx == 0) g_Ap[row * MST + step] = part + bcl;
    }
}

// ---------------- arc band gather ----------------
__global__ void k_arc(float* __restrict__ out) {
    size_t idx = (size_t)blockIdx.x * blockDim.x + threadIdx.x;
    size_t total = (size_t)BB * SL * SL;
    if (idx >= total) return;
    int c = (int)(idx % SL);
    int r = (int)((idx / SL) % SL);
    int b = (int)(idx / ((size_t)SL * SL));
    int start = r - MST; if (start < 0) start = 0;
    float v = 0.f;
    if (c >= start && c < r) v = g_Ap[(size_t)(b * SL + r) * MST + (c - start)];
    out[idx] = v;
}

// ---------------- host launcher ----------------
extern "C" void kernel_launch(void* const* d_in, const int* in_sizes, int n_in,
                              void* d_out, int out_size) {
    const float* input  = (const float*)d_in[0];
    const float* tagemb = (const float*)d_in[1];
    const int*   mask   = (const int*)d_in[2];
    const float* sent   = (const float*)d_in[3];
    const float* Wih_f  = (const float*)d_in[4];
    const float* Whh_f  = (const float*)d_in[5];
    const float* bih_f  = (const float*)d_in[6];
    const float* bhh_f  = (const float*)d_in[7];
    const float* Wih_b  = (const float*)d_in[8];
    const float* Whh_b  = (const float*)d_in[9];
    const float* bih_b  = (const float*)d_in[10];
    const float* bhh_b  = (const float*)d_in[11];
    const float* Wg2e   = (const float*)d_in[12];
    const float* bg2e   = (const float*)d_in[13];
    const float* Wih_e  = (const float*)d_in[14];
    const float* Whh_e  = (const float*)d_in[15];
    const float* bih_e  = (const float*)d_in[16];
    const float* bhh_e  = (const float*)d_in[17];
    const float* Wcls   = (const float*)d_in[18];
    const float* bcls   = (const float*)d_in[19];
    const float* bos    = (const float*)d_in[20];
    const float* Wht    = (const float*)d_in[21];
    const float* bht    = (const float*)d_in[22];
    const float* Wdt    = (const float*)d_in[23];
    const float* bdt    = (const float*)d_in[24];
    float* out = (float*)d_out;

    float *pX, *pPreF, *pPreB, *pGS, *pHe0, *pHe1;
    float *pWihfT, *pWihbT, *pWg2eT, *pWhheT, *pWhtT, *pWdtT;
    float *pbF, *pbB, *pbE;
    cudaGetSymbolAddress((void**)&pX, g_X);
    cudaGetSymbolAddress((void**)&pPreF, g_PreF);
    cudaGetSymbolAddress((void**)&pPreB, g_PreB);
    cudaGetSymbolAddress((void**)&pGS, g_GS);
    cudaGetSymbolAddress((void**)&pHe0, g_He0);
    cudaGetSymbolAddress((void**)&pHe1, g_He1);
    cudaGetSymbolAddress((void**)&pWihfT, g_WihfT);
    cudaGetSymbolAddress((void**)&pWihbT, g_WihbT);
    cudaGetSymbolAddress((void**)&pWg2eT, g_Wg2eT);
    cudaGetSymbolAddress((void**)&pWhheT, g_WhheT);
    cudaGetSymbolAddress((void**)&pWhtT, g_WhtT);
    cudaGetSymbolAddress((void**)&pWdtT, g_WdtT);
    cudaGetSymbolAddress((void**)&pbF, g_biasF);
    cudaGetSymbolAddress((void**)&pbB, g_biasB);
    cudaGetSymbolAddress((void**)&pbE, g_biasE);

    // weight transposes + combined biases
    k_transpose<<<(HG * DL + 255) / 256, 256>>>(Wih_f, pWihfT, HG, DL);
    k_transpose<<<(HG * DL + 255) / 256, 256>>>(Wih_b, pWihbT, HG, DL);
    k_transpose<<<(HEH * 2 * HG + 255) / 256, 256>>>(Wg2e, pWg2eT, HEH, 2 * HG);
    k_transpose<<<(HEH * HEH + 255) / 256, 256>>>(Whh_e, pWhheT, HEH, HEH);
    k_transpose<<<(TAGL * 2 * HG + 255) / 256, 256>>>(Wht, pWhtT, TAGL, 2 * HG);
    k_transpose<<<(TAGL * 2 * HG + 255) / 256, 256>>>(Wdt, pWdtT, TAGL, 2 * HG);
    k_vecadd<<<(HG + 255) / 256, 256>>>(bih_f, bhh_f, pbF, HG);
    k_vecadd<<<(HG + 255) / 256, 256>>>(bih_b, bhh_b, pbB, HG);
    k_vecadd<<<(HEH + 255) / 256, 256>>>(bih_e, bhh_e, pbE, HEH);

    // build X and mask floats
    {
        size_t n = (size_t)MR * DL;
        k_buildx<<<(unsigned)((n + 255) / 256), 256>>>(input, tagemb, sent);
        k_buildmf<<<(MR + 255) / 256, 256>>>(mask);
    }

    // Pre_f / Pre_b
    {
        dim3 grid((HG + 63) / 64, MR / 128);
        k_sgemm<0><<<grid, 256>>>(pX, pWihfT, pbF, pPreF, HG, DL);
        k_sgemm<0><<<grid, 256>>>(pX, pWihbT, pbB, pPreB, HG, DL);
    }

    // bidirectional recurrence (clusters of 8 CTAs; HW barrier)
    k_rnn<<<128, 256>>>(Whh_f, Whh_b);

    // proj -> He0
    {
        dim3 grid((HEH + 63) / 64, MR / 128);
        k_sgemm<0><<<grid, 256>>>(pGS, pWg2eT, bg2e, pHe0, HEH, 2 * HG);
    }

    // 20 estep iterations (ping-pong He)
    for (int k = 0; k < MST; k++) {
        const float* hin = (k & 1) ? pHe1 : pHe0;
        float* hout = (k & 1) ? pHe0 : pHe1;
        k_estep<<<MR / 64, 256>>>(hin, hout, Wih_e, Wcls, bcls, bos, k);
    }

    // head_tag / dep_tag straight into d_out
    {
        dim3 grid((TAGL + 63) / 64, MR / 128);
        k_sgemm<1><<<grid, 256>>>(pGS, pWhtT, bht, out, TAGL, 2 * HG);
        k_sgemm<1><<<grid, 256>>>(pGS, pWdtT, bdt, out + (size_t)MR * TAGL, TAGL, 2 * HG);
    }

    // arc logits
    {
        size_t total = (size_t)BB * SL * SL;
        k_arc<<<(unsigned)((total + 255) / 256), 256>>>(out + 2 * (size_t)MR * TAGL);
    }
    (void)in_sizes; (void)n_in; (void)out_size;
}

// round 5
// speedup vs baseline: 1.0566x; 1.0566x over previous
#include <cuda_runtime.h>
#include <cuda_bf16.h>
#include <math.h>

#define BB   64
#define TL   383
#define SL   384
#define DL   896
#define HG   400
#define HEH  256
#define TAGL 128
#define MST  20
#define MR   (BB*SL)    // 24576
#define NPRE 896        // padded 2*HG

// ---------------- scratch (device globals) ----------------
__device__ float g_X[(size_t)MR*DL];
__device__ float g_Mf[MR];
__device__ float g_Pre[(size_t)MR*NPRE];     // [row][dir*400 + j], cols 800..895 unused
__device__ float g_GS[(size_t)MR*2*HG];
__device__ float g_H[2*2*BB*HG];
__device__ float g_He0[(size_t)MR*HEH];
__device__ float g_He1[(size_t)MR*HEH];
__device__ float g_Ap[MR*MST];
__device__ float g_WihFBT[NPRE*NPRE];        // [k=896][n=896] cols 800.. zero
__device__ float g_Wg2eT[2*HG*HEH];
__device__ float g_WhheT[HEH*HEH];
__device__ float g_WtagT[2*HG*2*TAGL];       // [k=800][n=256] (ht | dt)
__device__ float g_biasFB[NPRE];
__device__ float g_biasE[HEH];
__device__ float g_biasTag[2*TAGL];

#define CLUSTER_SYNC_() do { \
    asm volatile("barrier.cluster.arrive.aligned;" ::: "memory"); \
    asm volatile("barrier.cluster.wait.aligned;" ::: "memory"); \
} while (0)

// ---------------- fused weight prep (all transposes + bias sums) ----------------
#define T1 (NPRE*NPRE)           // WihFBT
#define T2 (2*HG*HEH)            // Wg2eT
#define T3 (HEH*HEH)             // WhheT
#define T4 (2*HG*2*TAGL)         // WtagT
#define T5 (NPRE)                // biasFB
#define T6 (HEH)                 // biasE
#define T7 (2*TAGL)              // biasTag
#define TPREP (T1+T2+T3+T4+T5+T6+T7)

__global__ void k_prep(const float* __restrict__ Wih_f, const float* __restrict__ Wih_b,
                       const float* __restrict__ Wg2e, const float* __restrict__ Whh_e,
                       const float* __restrict__ Wht,  const float* __restrict__ Wdt,
                       const float* __restrict__ bih_f, const float* __restrict__ bhh_f,
                       const float* __restrict__ bih_b, const float* __restrict__ bhh_b,
                       const float* __restrict__ bih_e, const float* __restrict__ bhh_e,
                       const float* __restrict__ bht,   const float* __restrict__ bdt) {
    int idx = blockIdx.x * blockDim.x + threadIdx.x;
    if (idx < T1) {
        int k = idx / NPRE, n = idx % NPRE;
        float v = 0.f;
        if (n < HG)            v = Wih_f[(size_t)n * DL + k];
        else if (n < 2 * HG)   v = Wih_b[(size_t)(n - HG) * DL + k];
        if (k >= DL) v = 0.f;
        g_WihFBT[idx] = v;
        return;
    }
    idx -= T1;
    if (idx < T2) { int k = idx / HEH, n = idx % HEH; g_Wg2eT[idx] = Wg2e[(size_t)n * (2*HG) + k]; return; }
    idx -= T2;
    if (idx < T3) { int k = idx / HEH, n = idx % HEH; g_WhheT[idx] = Whh_e[(size_t)n * HEH + k]; return; }
    idx -= T3;
    if (idx < T4) {
        int k = idx / (2*TAGL), n = idx % (2*TAGL);
        g_WtagT[idx] = (n < TAGL) ? Wht[(size_t)n * (2*HG) + k] : Wdt[(size_t)(n - TAGL) * (2*HG) + k];
        return;
    }
    idx -= T4;
    if (idx < T5) {
        float v = 0.f;
        if (idx < HG) v = bih_f[idx] + bhh_f[idx];
        else if (idx < 2*HG) v = bih_b[idx-HG] + bhh_b[idx-HG];
        g_biasFB[idx] = v; return;
    }
    idx -= T5;
    if (idx < T6) { g_biasE[idx] = bih_e[idx] + bhh_e[idx]; return; }
    idx -= T6;
    if (idx < T7) { g_biasTag[idx] = (idx < TAGL) ? bht[idx] : bdt[idx - TAGL]; return; }
}

// ---------------- fused input build (X concat + mask floats) ----------------
__global__ void k_build(const float* __restrict__ inp, const float* __restrict__ tag,
                        const float* __restrict__ sent, const int* __restrict__ mask) {
    size_t idx = (size_t)blockIdx.x * blockDim.x + threadIdx.x;
    size_t nx = (size_t)MR * DL;
    if (idx < nx) {
        int d = (int)(idx % DL);
        int m = (int)(idx / DL);
        int b = m / SL, s = m % SL;
        float v;
        if (s == 0) v = sent[d];
        else {
            int t = s - 1;
            v = (d < 768) ? inp[(size_t)(b * TL + t) * 768 + d]
                          : tag[(size_t)(b * TL + t) * TAGL + (d - 768)];
        }
        g_X[idx] = v;
        return;
    }
    idx -= nx;
    if (idx < MR) {
        int b = (int)(idx / SL), s = (int)(idx % SL);
        g_Mf[idx] = (s == 0) ? 1.0f : (float)mask[b * TL + s - 1];
    }
}

// ---------------- 128x128 double-buffered SGEMM ----------------
// C(M,N) = A(M,K) @ Bt(K,N) + bias. A row stride == K. M%128==0, N%128==0, K%8==0.
// ACT=0: plain store (stride N). ACT=2: ELU + split store: blockIdx.x==0 -> C, ==1 -> C2 (stride 128).
template <int ACT>
__global__ __launch_bounds__(256) void k_gemm128(const float* __restrict__ A,
                                                 const float* __restrict__ Bt,
                                                 const float* __restrict__ bias,
                                                 float* __restrict__ C,
                                                 float* __restrict__ C2,
                                                 int N, int K) {
    __shared__ __align__(16) float As[2][8][132];
    __shared__ __align__(16) float Bs[2][8][132];
    int m0 = blockIdx.y * 128, n0 = blockIdx.x * 128;
    int tid = threadIdx.x;
    int tx = tid & 15, ty = tid >> 4;

    int arow = tid >> 1, akq = (tid & 1) * 4;
    const float* Ap = A + (size_t)(m0 + arow) * K + akq;
    int bkr = tid >> 5, bnq = (tid & 31) * 4;
    const float* Bp = Bt + (size_t)bkr * N + n0 + bnq;

    float acc[8][8];
#pragma unroll
    for (int i = 0; i < 8; i++)
#pragma unroll
        for (int j = 0; j < 8; j++) acc[i][j] = 0.f;

    // preload tile 0
    float4 av = *(const float4*)Ap;
    float4 bv = *(const float4*)Bp;
    As[0][akq + 0][arow] = av.x;
    As[0][akq + 1][arow] = av.y;
    As[0][akq + 2][arow] = av.z;
    As[0][akq + 3][arow] = av.w;
    *(float4*)&Bs[0][bkr][bnq] = bv;
    __syncthreads();

    int nk = K >> 3;
    for (int kt = 0; kt < nk; kt++) {
        int buf = kt & 1;
        if (kt + 1 < nk) {
            av = *(const float4*)(Ap + (kt + 1) * 8);
            bv = *(const float4*)(Bp + (size_t)(kt + 1) * 8 * N);
        }
#pragma unroll
        for (int kk = 0; kk < 8; kk++) {
            float a[8], b[8];
            *(float4*)(a)     = *(const float4*)&As[buf][kk][ty * 8];
            *(float4*)(a + 4) = *(const float4*)&As[buf][kk][ty * 8 + 4];
            *(float4*)(b)     = *(const float4*)&Bs[buf][kk][tx * 8];
            *(float4*)(b + 4) = *(const float4*)&Bs[buf][kk][tx * 8 + 4];
#pragma unroll
            for (int i = 0; i < 8; i++)
#pragma unroll
                for (int j = 0; j < 8; j++) acc[i][j] += a[i] * b[j];
        }
        if (kt + 1 < nk) {
            int nb = buf ^ 1;
            As[nb][akq + 0][arow] = av.x;
            As[nb][akq + 1][arow] = av.y;
            As[nb][akq + 2][arow] = av.z;
            As[nb][akq + 3][arow] = av.w;
            *(float4*)&Bs[nb][bkr][bnq] = bv;
        }
        __syncthreads();
    }

    float bj[8];
#pragma unroll
    for (int j = 0; j < 8; j++) bj[j] = bias[n0 + tx * 8 + j];

    if (ACT == 0) {
#pragma unroll
        for (int i = 0; i < 8; i++) {
            int row = m0 + ty * 8 + i;
            float v[8];
#pragma unroll
            for (int j = 0; j < 8; j++) v[j] = acc[i][j] + bj[j];
            *(float4*)(C + (size_t)row * N + n0 + tx * 8)     = *(float4*)(v);
            *(float4*)(C + (size_t)row * N + n0 + tx * 8 + 4) = *(float4*)(v + 4);
        }
    } else {
        float* dst = (blockIdx.x == 0) ? C : C2;
#pragma unroll
        for (int i = 0; i < 8; i++) {
            int row = m0 + ty * 8 + i;
            float v[8];
#pragma unroll
            for (int j = 0; j < 8; j++) {
                float x = acc[i][j] + bj[j];
                v[j] = (x > 0.f) ? x : expm1f(x);
            }
            *(float4*)(dst + (size_t)row * TAGL + tx * 8)     = *(float4*)(v);
            *(float4*)(dst + (size_t)row * TAGL + tx * 8 + 4) = *(float4*)(v + 4);
        }
    }
}

// ---------------- persistent bidirectional masked RNN (cluster-synced) ----------------
__global__ void __cluster_dims__(8, 1, 1) __launch_bounds__(256, 1)
k_rnn(const float* __restrict__ WhhF, const float* __restrict__ WhhB) {
    int bx = blockIdx.x;
    int dir = bx >> 6;
    int bid = bx & 63;
    int bg = bid >> 3;
    int jg = bid & 7;
    const float* Whh = dir ? WhhB : WhhF;
    int jbase = jg * 50, b0 = bg * 8;
    int tid = threadIdx.x;
    int jl = tid >> 3, kp = tid & 7;
    bool jact = (jl < 25);
    int j0 = jbase + jl * 2;
    int preoff = dir * HG;

    float w0[50], w1[50];
    if (jact) {
#pragma unroll
        for (int i = 0; i < 50; i++) {
            w0[i] = Whh[(size_t)j0 * HG + kp * 50 + i];
            w1[i] = Whh[(size_t)(j0 + 1) * HG + kp * 50 + i];
        }
    }
    float* Hp0 = g_H + dir * 2 * BB * HG;
    float* Hp1 = Hp0 + BB * HG;
    for (int idx = tid; idx < 400; idx += 256) {
        int bl = idx / 50, jj = idx % 50;
        __stcg(&Hp0[(b0 + bl) * HG + jbase + jj], 0.f);
        __stcg(&Hp1[(b0 + bl) * HG + jbase + jj], 0.f);
    }
    CLUSTER_SYNC_();

    __shared__ __align__(16) float Hs[8 * HG];

    for (int tv = 0; tv < SL; tv++) {
        int t = dir ? (SL - 1 - tv) : tv;
        float* Hcur = (tv & 1) ? Hp1 : Hp0;
        float* Hnxt = (tv & 1) ? Hp0 : Hp1;
        for (int idx = tid; idx < 8 * HG; idx += 256)
            Hs[idx] = __ldcg(&Hcur[(b0 + (idx / HG)) * HG + (idx % HG)]);
        __syncthreads();

        float s0v[8], s1v[8];
        if (jact) {
#pragma unroll
            for (int bl = 0; bl < 8; bl++) {
                const float2* hv = (const float2*)(Hs + bl * HG + kp * 50);
                float a0 = 0.f, a1 = 0.f, c0 = 0.f, c1 = 0.f;
#pragma unroll
                for (int i = 0; i < 25; i++) {
                    float2 h = hv[i];
                    a0 += w0[2 * i] * h.x;  c0 += w0[2 * i + 1] * h.y;
                    a1 += w1[2 * i] * h.x;  c1 += w1[2 * i + 1] * h.y;
                }
                s0v[bl] = a0 + c0;
                s1v[bl] = a1 + c1;
            }
        } else {
#pragma unroll
            for (int bl = 0; bl < 8; bl++) { s0v[bl] = 0.f; s1v[bl] = 0.f; }
        }
#pragma unroll
        for (int bl = 0; bl < 8; bl++) {
            float s0 = s0v[bl], s1 = s1v[bl];
            s0 += __shfl_xor_sync(0xffffffffu, s0, 1);
            s0 += __shfl_xor_sync(0xffffffffu, s0, 2);
            s0 += __shfl_xor_sync(0xffffffffu, s0, 4);
            s1 += __shfl_xor_sync(0xffffffffu, s1, 1);
            s1 += __shfl_xor_sync(0xffffffffu, s1, 2);
            s1 += __shfl_xor_sync(0xffffffffu, s1, 4);
            if (jact && kp == 0) {
                int b = b0 + bl;
                int mrow = b * SL + t;
                float mt = g_Mf[mrow];
                float om = 1.f - mt;
                size_t pbase = (size_t)mrow * NPRE + preoff;
                float h00 = Hs[bl * HG + j0];
                float h01 = Hs[bl * HG + j0 + 1];
                float hn0 = tanhf(g_Pre[pbase + j0] + s0);
                float hn1 = tanhf(g_Pre[pbase + j0 + 1] + s1);
                float u0 = mt * hn0 + om * h00;
                float u1 = mt * hn1 + om * h01;
                __stcg(&Hnxt[b * HG + j0], u0);
                __stcg(&Hnxt[b * HG + j0 + 1], u1);
                size_t gbase = (size_t)mrow * (2 * HG) + dir * HG;
                g_GS[gbase + j0] = u0 * mt;
                g_GS[gbase + j0 + 1] = u1 * mt;
            }
        }
        CLUSTER_SYNC_();
    }
}

// ---------------- estep: double-buffered, logit fused ----------------
// BM=64, BN=256(full), BK=8, 256 threads, 8x8 per-thread tile.
__global__ __launch_bounds__(256) void k_estep(const float* __restrict__ Hin,
                                               float* __restrict__ Hout,
                                               const float* __restrict__ wie,
                                               const float* __restrict__ wcls,
                                               const float* __restrict__ bcls,
                                               const float* __restrict__ bos, int step) {
    __shared__ __align__(16) float As[2][8][68];
    __shared__ __align__(16) float Bs[2][8][260];
    int m0 = blockIdx.x * 64;
    int tid = threadIdx.x;
    int tx = tid & 31, ty = tid >> 5;

    int arow = tid >> 1, akq = (tid & 1) * 4;     // valid when tid<128
    const float* Ap = Hin + (size_t)(m0 + arow) * HEH + akq;
    int bkr0 = tid >> 6, bnq0 = (tid & 63) * 4;   // first half of B tile
    const float* Bp0 = g_WhheT + (size_t)bkr0 * HEH + bnq0;
    const float* Bp1 = g_WhheT + (size_t)(bkr0 + 4) * HEH + bnq0;

    float acc[8][8];
#pragma unroll
    for (int i = 0; i < 8; i++)
#pragma unroll
        for (int j = 0; j < 8; j++) acc[i][j] = 0.f;

    float4 av = make_float4(0.f, 0.f, 0.f, 0.f);
    if (tid < 128) av = *(const float4*)Ap;
    float4 bv0 = *(const float4*)Bp0;
    float4 bv1 = *(const float4*)Bp1;
    if (tid < 128) {
        As[0][akq + 0][arow] = av.x;
        As[0][akq + 1][arow] = av.y;
        As[0][akq + 2][arow] = av.z;
        As[0][akq + 3][arow] = av.w;
    }
    *(float4*)&Bs[0][bkr0][bnq0]     = bv0;
    *(float4*)&Bs[0][bkr0 + 4][bnq0] = bv1;
    __syncthreads();

    const int nk = HEH >> 3;   // 32
    for (int kt = 0; kt < nk; kt++) {
        int buf = kt & 1;
        if (kt + 1 < nk) {
            if (tid < 128) av = *(const float4*)(Ap + (kt + 1) * 8);
            bv0 = *(const float4*)(Bp0 + (size_t)(kt + 1) * 8 * HEH);
            bv1 = *(const float4*)(Bp1 + (size_t)(kt + 1) * 8 * HEH);
        }
#pragma unroll
        for (int kk = 0; kk < 8; kk++) {
            float a[8], b[8];
            *(float4*)(a)     = *(const float4*)&As[buf][kk][ty * 8];
            *(float4*)(a + 4) = *(const float4*)&As[buf][kk][ty * 8 + 4];
            *(float4*)(b)     = *(const float4*)&Bs[buf][kk][tx * 8];
            *(float4*)(b + 4) = *(const float4*)&Bs[buf][kk][tx * 8 + 4];
#pragma unroll
            for (int i = 0; i < 8; i++)
#pragma unroll
                for (int j = 0; j < 8; j++) acc[i][j] += a[i] * b[j];
        }
        if (kt + 1 < nk) {
            int nb = buf ^ 1;
            if (tid < 128) {
                As[nb][akq + 0][arow] = av.x;
                As[nb][akq + 1][arow] = av.y;
                As[nb][akq + 2][arow] = av.z;
                As[nb][akq + 3][arow] = av.w;
            }
            *(float4*)&Bs[nb][bkr0][bnq0]     = bv0;
            *(float4*)&Bs[nb][bkr0 + 4][bnq0] = bv1;
        }
        __syncthreads();
    }

    float bcl = bcls[0];
    float be[8], wi[8], wc[8];
#pragma unroll
    for (int j = 0; j < 8; j++) {
        int col = tx * 8 + j;
        be[j] = g_biasE[col];
        wi[j] = wie[col];
        wc[j] = wcls[col];
    }
#pragma unroll
    for (int i = 0; i < 8; i++) {
        int row = m0 + ty * 8 + i;
        float xe = (step == 0) ? bos[0] : g_Ap[row * MST + step - 1];
        float part = 0.f;
        float hn[8];
#pragma unroll
        for (int j = 0; j < 8; j++) {
            float v = tanhf(acc[i][j] + be[j] + xe * wi[j]);
            hn[j] = v;
            part += v * wc[j];
        }
        *(float4*)(Hout + (size_t)row * HEH + tx * 8)     = *(float4*)(hn);
        *(float4*)(Hout + (size_t)row * HEH + tx * 8 + 4) = *(float4*)(hn + 4);
#pragma unroll
        for (int off = 16; off > 0; off >>= 1)
            part += __shfl_xor_sync(0xffffffffu, part, off);
        if (tx == 0) g_Ap[row * MST + step] = part + bcl;
    }
}

// ---------------- arc band gather ----------------
__global__ void k_arc(float* __restrict__ out) {
    size_t idx = (size_t)blockIdx.x * blockDim.x + threadIdx.x;
    size_t total = (size_t)BB * SL * SL;
    if (idx >= total) return;
    int c = (int)(idx % SL);
    int r = (int)((idx / SL) % SL);
    int b = (int)(idx / ((size_t)SL * SL));
    int start = r - MST; if (start < 0) start = 0;
    float v = 0.f;
    if (c >= start && c < r) v = g_Ap[(size_t)(b * SL + r) * MST + (c - start)];
    out[idx] = v;
}

// ---------------- host launcher ----------------
extern "C" void kernel_launch(void* const* d_in, const int* in_sizes, int n_in,
                              void* d_out, int out_size) {
    const float* input  = (const float*)d_in[0];
    const float* tagemb = (const float*)d_in[1];
    const int*   mask   = (const int*)d_in[2];
    const float* sent   = (const float*)d_in[3];
    const float* Wih_f  = (const float*)d_in[4];
    const float* Whh_f  = (const float*)d_in[5];
    const float* bih_f  = (const float*)d_in[6];
    const float* bhh_f  = (const float*)d_in[7];
    const float* Wih_b  = (const float*)d_in[8];
    const float* Whh_b  = (const float*)d_in[9];
    const float* bih_b  = (const float*)d_in[10];
    const float* bhh_b  = (const float*)d_in[11];
    const float* Wg2e   = (const float*)d_in[12];
    const float* bg2e   = (const float*)d_in[13];
    const float* Wih_e  = (const float*)d_in[14];
    const float* Whh_e  = (const float*)d_in[15];
    const float* bih_e  = (const float*)d_in[16];
    const float* bhh_e  = (const float*)d_in[17];
    const float* Wcls   = (const float*)d_in[18];
    const float* bcls   = (const float*)d_in[19];
    const float* bos    = (const float*)d_in[20];
    const float* Wht    = (const float*)d_in[21];
    const float* bht    = (const float*)d_in[22];
    const float* Wdt    = (const float*)d_in[23];
    const float* bdt    = (const float*)d_in[24];
    float* out = (float*)d_out;

    float *pX, *pPre, *pGS, *pHe0, *pHe1;
    float *pWihFBT, *pWg2eT, *pWtagT, *pbFB, *pbTag;
    cudaGetSymbolAddress((void**)&pX, g_X);
    cudaGetSymbolAddress((void**)&pPre, g_Pre);
    cudaGetSymbolAddress((void**)&pGS, g_GS);
    cudaGetSymbolAddress((void**)&pHe0, g_He0);
    cudaGetSymbolAddress((void**)&pHe1, g_He1);
    cudaGetSymbolAddress((void**)&pWihFBT, g_WihFBT);
    cudaGetSymbolAddress((void**)&pWg2eT, g_Wg2eT);
    cudaGetSymbolAddress((void**)&pWtagT, g_WtagT);
    cudaGetSymbolAddress((void**)&pbFB, g_biasFB);
    cudaGetSymbolAddress((void**)&pbTag, g_biasTag);

    // 1. fused weight prep
    k_prep<<<(TPREP + 255) / 256, 256>>>(Wih_f, Wih_b, Wg2e, Whh_e, Wht, Wdt,
                                         bih_f, bhh_f, bih_b, bhh_b,
                                         bih_e, bhh_e, bht, bdt);
    // 2. fused input build
    {
        size_t n = (size_t)MR * DL + MR;
        k_build<<<(unsigned)((n + 255) / 256), 256>>>(input, tagemb, sent, mask);
    }
    // 3. fused Pre GEMM (N=896 padded)
    {
        dim3 grid(NPRE / 128, MR / 128);
        k_gemm128<0><<<grid, 256>>>(pX, pWihFBT, pbFB, pPre, nullptr, NPRE, DL);
    }
    // 4. bidirectional recurrence
    k_rnn<<<128, 256>>>(Whh_f, Whh_b);
    // 5. proj -> He0
    {
        dim3 grid(HEH / 128, MR / 128);
        k_gemm128<0><<<grid, 256>>>(pGS, pWg2eT, bg2e, pHe0, nullptr, HEH, 2 * HG);
    }
    // 6..25: estep chain  (launch #6 is ncu's capture target)
    for (int k = 0; k < MST; k++) {
        const float* hin = (k & 1) ? pHe1 : pHe0;
        float* hout = (k & 1) ? pHe0 : pHe1;
        k_estep<<<MR / 64, 256>>>(hin, hout, Wih_e, Wcls, bcls, bos, k);
    }
    // head_tag / dep_tag fused GEMM -> d_out
    {
        dim3 grid(2, MR / 128);
        k_gemm128<2><<<grid, 256>>>(pGS, pWtagT, pbTag, out, out + (size_t)MR * TAGL,
                                    2 * TAGL, 2 * HG);
    }
    // arc logits
    {
        size_t total = (size_t)BB * SL * SL;
        k_arc<<<(unsigned)((total + 255) / 256), 256>>>(out + 2 * (size_t)MR * TAGL);
    }
    (void)in_sizes; (void)n_in; (void)out_size;
}